// round 1
// baseline (speedup 1.0000x reference)
#include <cuda_runtime.h>
#include <math.h>

#define MAXN 100000
#define F 32

// Scratch (no allocs allowed): ping-pong feature buffers + degree/scale + pooled max.
__device__ float g_A1[MAXN * F];   // hs1 (gather source, layer 1)
__device__ float g_B1[MAXN * F];   // accumulation target, layer 1
__device__ float g_A2[MAXN * F];   // hs2 (gather source, layer 2)
__device__ float g_B2[MAXN * F];   // accumulation target, layer 2
__device__ int   g_deg[MAXN];
__device__ float g_dinv[MAXN];
__device__ int   g_max[F];         // float-as-int max (values >= 0 after relu)
__device__ int   g_is64;           // edge_index dtype flag (1 = int64, 0 = int32)

// ---------------------------------------------------------------------------
// Init: zero degree histogram + pooled max, and detect edge_index width.
// For int64 indices < 2^31 every odd 32-bit word is 0; for int32 the odd words
// are random node ids (P(128 consecutive zeros) ~ 0).
__global__ void k_init(const int* __restrict__ ew, int n) {
    int i = blockIdx.x * blockDim.x + threadIdx.x;
    if (i < n) g_deg[i] = 0;
    if (i < F) g_max[i] = 0;
    if (blockIdx.x == 0 && threadIdx.x == 0) {
        int all_zero = 1;
        #pragma unroll 1
        for (int k = 0; k < 128; k++) {
            if (ew[2 * k + 1] != 0) { all_zero = 0; break; }
        }
        g_is64 = all_zero;
    }
}

__device__ __forceinline__ int load_idx(const int* __restrict__ ew, int is64, long long pos) {
    // pos = linear element index into edge_index viewed as its native dtype.
    return is64 ? ew[2 * pos] : ew[pos];   // little-endian low word for int64
}

// ---------------------------------------------------------------------------
// Degree histogram over dst (in-degree).
__global__ void k_deg(const int* __restrict__ ew, int E) {
    int e = blockIdx.x * blockDim.x + threadIdx.x;
    if (e >= E) return;
    int is64 = g_is64;
    int dst = load_idx(ew, is64, (long long)E + e);
    atomicAdd(&g_deg[dst], 1);
}

__global__ void k_dinv(int n) {
    int i = blockIdx.x * blockDim.x + threadIdx.x;
    if (i < n) g_dinv[i] = rsqrtf((float)(g_deg[i] + 1));
}

// ---------------------------------------------------------------------------
// Layer-1 node transform: hs1[i,:] = (x[i,:] @ W1) * dinv[i]; init both buffers.
// One warp per node, lane = output feature.
__global__ void k_lin1(const float* __restrict__ x, const float* __restrict__ W1, int n) {
    __shared__ float sW[8 * F];
    int t = threadIdx.x;
    if (t < 8 * F) sW[t] = W1[t];
    __syncthreads();
    int i = blockIdx.x * (blockDim.x >> 5) + (t >> 5);
    int j = t & 31;
    if (i >= n) return;
    const float* xr = x + i * 8;
    float acc = 0.f;
    #pragma unroll
    for (int k = 0; k < 8; k++) acc += xr[k] * sW[k * F + j];
    acc *= g_dinv[i];
    g_A1[i * F + j] = acc;
    g_B1[i * F + j] = acc;
}

// ---------------------------------------------------------------------------
// Edge scatter: B[dst,:] += A[src,:], 8 threads per edge, float4 + red.v4.
__global__ void k_edge(const int* __restrict__ ew, int E, int layer) {
    long long gid = (long long)blockIdx.x * blockDim.x + threadIdx.x;
    long long total = (long long)E * 8;
    if (gid >= total) return;
    int e = (int)(gid >> 3);
    int q = (int)(gid & 7);
    int is64 = g_is64;
    int src = load_idx(ew, is64, e);
    int dst = load_idx(ew, is64, (long long)E + e);
    const float4* A4 = (const float4*)(layer ? g_A2 : g_A1);
    float* B = layer ? g_B2 : g_B1;
    float4 v = A4[src * 8 + q];
    float* p = B + dst * F + q * 4;
    asm volatile("red.global.add.v4.f32 [%0], {%1,%2,%3,%4};"
                 :: "l"(p), "f"(v.x), "f"(v.y), "f"(v.z), "f"(v.w)
                 : "memory");
}

// ---------------------------------------------------------------------------
// Layer-2 node transform: t = relu(B1[i,:]*dinv + b1); hs2 = (t @ W2) * dinv.
// One warp per node; t broadcast across lanes via shfl.
__global__ void k_layer2(const float* __restrict__ b1, const float* __restrict__ W2, int n) {
    __shared__ float sW[F * F];
    int t = threadIdx.x;
    for (int k = t; k < F * F; k += blockDim.x) sW[k] = W2[k];
    __syncthreads();
    int i = blockIdx.x * (blockDim.x >> 5) + (t >> 5);
    int j = t & 31;
    if (i >= n) return;
    float di = g_dinv[i];
    float v = fmaxf(g_B1[i * F + j] * di + b1[j], 0.f);
    float acc = 0.f;
    #pragma unroll
    for (int k = 0; k < F; k++) {
        float vk = __shfl_sync(0xffffffffu, v, k);
        acc += vk * sW[k * F + j];
    }
    acc *= di;
    g_A2[i * F + j] = acc;
    g_B2[i * F + j] = acc;
}

// ---------------------------------------------------------------------------
// Global max pool over relu(B2*dinv + b2). Two-stage: per-thread strided max,
// shared reduce over 8 node-slots, then one atomicMax per feature per block
// (avoids hot-spotting 3.2M atomics on 32 addresses).
__global__ void k_final(const float* __restrict__ b2, int n) {
    __shared__ float sm[8][F];
    int t = threadIdx.x;
    int j = t & 31, s = t >> 5;
    float bj = b2[j];
    float m = 0.f;  // relu lower bound
    for (int i = blockIdx.x * 8 + s; i < n; i += gridDim.x * 8) {
        float v = g_B2[i * F + j] * g_dinv[i] + bj;
        m = fmaxf(m, v);
    }
    sm[s][j] = m;
    __syncthreads();
    if (s == 0) {
        float mm = sm[0][j];
        #pragma unroll
        for (int k = 1; k < 8; k++) mm = fmaxf(mm, sm[k][j]);
        atomicMax(&g_max[j], __float_as_int(mm));
    }
}

// ---------------------------------------------------------------------------
// FC + log_softmax on the pooled 32-vector (trivial work, single thread).
__global__ void k_fc(const float* __restrict__ fcW, const float* __restrict__ fcb,
                     float* __restrict__ out) {
    if (threadIdx.x != 0) return;
    float g[F];
    #pragma unroll
    for (int j = 0; j < F; j++) g[j] = __int_as_float(g_max[j]);
    float lg[5];
    float mx = -1e30f;
    #pragma unroll
    for (int c = 0; c < 5; c++) {
        float a = fcb[c];
        #pragma unroll
        for (int j = 0; j < F; j++) a += g[j] * fcW[j * 5 + c];
        lg[c] = a;
        mx = fmaxf(mx, a);
    }
    float sum = 0.f;
    #pragma unroll
    for (int c = 0; c < 5; c++) sum += expf(lg[c] - mx);
    float l = logf(sum) + mx;
    #pragma unroll
    for (int c = 0; c < 5; c++) out[c] = lg[c] - l;
}

// ---------------------------------------------------------------------------
extern "C" void kernel_launch(void* const* d_in, const int* in_sizes, int n_in,
                              void* d_out, int out_size) {
    const float* x   = (const float*)d_in[0];
    const int*   ew  = (const int*)d_in[1];   // edge_index words (int32 view)
    const float* W1  = (const float*)d_in[2];
    const float* b1  = (const float*)d_in[3];
    const float* W2  = (const float*)d_in[4];
    const float* b2  = (const float*)d_in[5];
    const float* fcW = (const float*)d_in[6];
    const float* fcb = (const float*)d_in[7];
    float* out = (float*)d_out;

    int n = in_sizes[0] / 8;       // 100000
    int E = in_sizes[1] / 2;       // 1600000

    k_init<<<(n + 255) / 256, 256>>>(ew, n);
    k_deg<<<(E + 255) / 256, 256>>>(ew, E);
    k_dinv<<<(n + 255) / 256, 256>>>(n);
    k_lin1<<<(n + 7) / 8, 256>>>(x, W1, n);

    long long work = (long long)E * 8;
    int eb = (int)((work + 255) / 256);
    k_edge<<<eb, 256>>>(ew, E, 0);
    k_layer2<<<(n + 7) / 8, 256>>>(b1, W2, n);
    k_edge<<<eb, 256>>>(ew, E, 1);

    k_final<<<512, 256>>>(b2, n);
    k_fc<<<1, 32>>>(fcW, fcb, out);
}